// round 11
// baseline (speedup 1.0000x reference)
#include <cuda_runtime.h>
#include <stdint.h>
#include <math.h>

#define B_ROWS 16384
#define N_G    8192
#define D      256
#define MT     128
#define NTile  128
#define NTILES (N_G / NTile)        // 64

#define STR    272                  // bytes per row in SMEM tiles (256 + 16 pad)

#define SM_A_BYTES (MT * STR)                  // 34816
#define QG_BYTES   (NTile * STR)               // 34816
#define SG_BYTES   512
#define STAGE      (QG_BYTES + SG_BYTES)       // 35328
#define SM_BS      SM_A_BYTES
#define SM_TOP     (SM_BS + 3 * STAGE)         // 140800
#define SM_WIN     (SM_TOP + 6144)
#define SMEM_TOTAL (SM_WIN + 512)              // 147456

#define REPAIR_T   0.08f

// ---------------- device scratch ----------------
__device__ uint4                d_qx_v4[B_ROWS * D / 16];   // int8 x
__device__ uint4                d_qg_v4[N_G * D / 16];      // int8 normalized g
__device__ __align__(16) float  d_sx[B_ROWS];
__device__ __align__(16) float  d_sg[N_G];
__device__ __align__(16) float  d_rnorm[N_G];
__device__ float                d_sums[N_G * D];
__device__ unsigned int         d_counts[N_G];

// ---------------- helpers ----------------
__device__ __forceinline__ uint32_t smem_u32(const void* p) {
    uint32_t a;
    asm("{ .reg .u64 t; cvta.to.shared.u64 t, %1; cvt.u32.u64 %0, t; }" : "=r"(a) : "l"(p));
    return a;
}
__device__ __forceinline__ void ldm_x4(uint32_t r[4], uint32_t addr) {
    asm volatile("ldmatrix.sync.aligned.m8n8.x4.shared.b16 {%0,%1,%2,%3}, [%4];"
                 : "=r"(r[0]), "=r"(r[1]), "=r"(r[2]), "=r"(r[3]) : "r"(addr));
}
__device__ __forceinline__ void mma_s8(int c[4], const uint32_t a[4], const uint32_t b[2]) {
    asm volatile(
        "mma.sync.aligned.m16n8k32.row.col.s32.s8.s8.s32 "
        "{%0,%1,%2,%3}, {%4,%5,%6,%7}, {%8,%9}, {%0,%1,%2,%3};"
        : "+r"(c[0]), "+r"(c[1]), "+r"(c[2]), "+r"(c[3])
        : "r"(a[0]), "r"(a[1]), "r"(a[2]), "r"(a[3]), "r"(b[0]), "r"(b[1]));
}
__device__ __forceinline__ void top3_ins(float v, int i,
                                         float& b1, int& i1, float& b2, int& i2,
                                         float& b3, int& i3) {
    if (v > b1 || (v == b1 && i < i1)) { b3 = b2; i3 = i2; b2 = b1; i2 = i1; b1 = v; i1 = i; }
    else if (v > b2 || (v == b2 && i < i2)) { b3 = b2; i3 = i2; b2 = v; i2 = i; }
    else if (v > b3 || (v == b3 && i < i3)) { b3 = v; i3 = i; }
}
__device__ __forceinline__ int pack4(int q0, int q1, int q2, int q3) {
    return (q0 & 255) | ((q1 & 255) << 8) | ((q2 & 255) << 16) | (q3 << 24);
}

// ---------------------------------------------------------------------------
// prep_x: per-row int8 quantization of x. 8 warps/block, 1 warp per row.
// ---------------------------------------------------------------------------
__global__ void __launch_bounds__(256) prep_x_kernel(const float* __restrict__ x) {
    int wid  = threadIdx.x >> 5;
    int lane = threadIdx.x & 31;
    int row  = blockIdx.x * 8 + wid;

    float4 v0 = *(const float4*)&x[(size_t)row * D + lane * 4];
    float4 v1 = *(const float4*)&x[(size_t)row * D + 128 + lane * 4];
    float m = fmaxf(fmaxf(fabsf(v0.x), fabsf(v0.y)), fmaxf(fabsf(v0.z), fabsf(v0.w)));
    m = fmaxf(m, fmaxf(fmaxf(fabsf(v1.x), fabsf(v1.y)), fmaxf(fabsf(v1.z), fabsf(v1.w))));
    #pragma unroll
    for (int o = 16; o; o >>= 1) m = fmaxf(m, __shfl_xor_sync(0xFFFFFFFFu, m, o));

    float s   = m * (1.0f / 127.0f);
    float inv = (m > 0.0f) ? 127.0f / m : 0.0f;
    if (lane == 0) d_sx[row] = s;

    int* qw = (int*)d_qx_v4;
    qw[row * 64 + lane] = pack4(__float2int_rn(v0.x * inv), __float2int_rn(v0.y * inv),
                                __float2int_rn(v0.z * inv), __float2int_rn(v0.w * inv));
    qw[row * 64 + 32 + lane] = pack4(__float2int_rn(v1.x * inv), __float2int_rn(v1.y * inv),
                                     __float2int_rn(v1.z * inv), __float2int_rn(v1.w * inv));
}

// ---------------------------------------------------------------------------
// prep_g: normalize g, per-row int8 quantize; zero sums/counts; keep rnorm/sg
// ---------------------------------------------------------------------------
__global__ void __launch_bounds__(256) prep_g_kernel(const float* __restrict__ gf) {
    __shared__ float red[8];
    __shared__ float srn, sinv;
    __shared__ __align__(16) char qbuf[256];

    int g = blockIdx.x;
    int t = threadIdx.x;
    float v = gf[g * D + t];
    d_sums[g * D + t] = 0.0f;

    float s = v * v;
    #pragma unroll
    for (int o = 16; o; o >>= 1) s += __shfl_xor_sync(0xFFFFFFFFu, s, o);
    if ((t & 31) == 0) red[t >> 5] = s;
    __syncthreads();
    if (t < 8) {
        float r = red[t];
        #pragma unroll
        for (int o = 4; o; o >>= 1) r += __shfl_xor_sync(0xFFu, r, o);
        if (t == 0) {
            srn = 1.0f / fmaxf(sqrtf(r), 1e-12f);
            d_rnorm[g] = srn;
            d_counts[g] = 0u;
        }
    }
    __syncthreads();
    float gn = v * srn;

    float m = fabsf(gn);
    #pragma unroll
    for (int o = 16; o; o >>= 1) m = fmaxf(m, __shfl_xor_sync(0xFFFFFFFFu, m, o));
    if ((t & 31) == 0) red[t >> 5] = m;
    __syncthreads();
    if (t < 8) {
        float r = red[t];
        #pragma unroll
        for (int o = 4; o; o >>= 1) r = fmaxf(r, __shfl_xor_sync(0xFFu, r, o));
        if (t == 0) {
            d_sg[g] = r * (1.0f / 127.0f);
            sinv = (r > 0.0f) ? 127.0f / r : 0.0f;
        }
    }
    __syncthreads();
    qbuf[t] = (char)__float2int_rn(gn * sinv);
    __syncthreads();
    if (t < 16) d_qg_v4[g * 16 + t] = *(uint4*)&qbuf[t * 16];
}

// ---------------------------------------------------------------------------
// main: s8 m16n8k32 IMMA + top-3 argmax + exact fp32 repair + segment-sum
//   128 CTAs x 256 thr; 8 warps 4(M)x2(N); warp tile 32x64
// ---------------------------------------------------------------------------
__global__ void __launch_bounds__(256, 1)
assign_kernel(const float* __restrict__ x, const float* __restrict__ gf) {
    extern __shared__ char smem[];
    char*  As   = smem;                           // [128][272] int8
    char*  St   = smem + SM_BS;                   // 3 stages: qg tile + sg floats
    float* b1_s = (float*)(smem + SM_TOP);        // [256] per (row, wn)
    float* b2_s = b1_s + 256;
    float* b3_s = b2_s + 256;
    int*   i1_s = (int*)(b3_s + 256);
    int*   i2_s = i1_s + 256;
    int*   i3_s = i2_s + 256;
    int*   swin = (int*)(smem + SM_WIN);

    const int tid  = threadIdx.x;
    const int lane = tid & 31;
    const int wid  = tid >> 5;
    const int wm   = wid >> 1;
    const int wn   = wid & 1;
    const int l4   = lane >> 2;
    const int lq   = lane & 3;
    const int g8   = lane >> 3;
    const int r8   = lane & 7;
    const int bm   = blockIdx.x * MT;

    // ---- load A (int8 x rows) into SMEM ----
    for (int i = tid; i < MT * 16; i += 256) {
        int m = i >> 4, q = i & 15;
        *(uint4*)(As + m * STR + q * 16) = d_qx_v4[(size_t)(bm + m) * 16 + q];
    }

    // ---- per-thread x scales for the 4 accumulator rows ----
    float sx[2][2];
    #pragma unroll
    for (int mt = 0; mt < 2; mt++)
        #pragma unroll
        for (int h = 0; h < 2; h++)
            sx[mt][h] = d_sx[bm + wm * 32 + mt * 16 + h * 8 + l4];

    // ---- ldmatrix row-base addresses ----
    uint32_t aRow[2];
    #pragma unroll
    for (int mt = 0; mt < 2; mt++)
        aRow[mt] = smem_u32(As) + (wm * 32 + mt * 16 + (g8 & 1) * 8 + r8) * STR + (g8 >> 1) * 16;
    uint32_t bRow[4];
    #pragma unroll
    for (int p = 0; p < 4; p++)
        bRow[p] = smem_u32(St) + (wn * 64 + p * 16 + (g8 >> 1) * 8 + r8) * STR + (g8 & 1) * 16;

    // ---- stage prefetch ----
    const int nrow = tid >> 1;
    const int half = tid & 1;
    auto prefetch = [&](int tile) {
        char* dst = St + (tile % 3) * STAGE;
        const char* src = (const char*)d_qg_v4 + (size_t)(tile * NTile + nrow) * D + half * 128;
        uint32_t d0 = smem_u32(dst + nrow * STR + half * 128);
        #pragma unroll
        for (int q = 0; q < 8; q++)
            asm volatile("cp.async.cg.shared.global [%0], [%1], 16;"
                         :: "r"(d0 + q * 16), "l"(src + q * 16));
        if (tid < 32) {
            uint32_t ds = smem_u32(dst + QG_BYTES + tid * 16);
            const float* ss = &d_sg[tile * NTile + tid * 4];
            asm volatile("cp.async.cg.shared.global [%0], [%1], 16;"
                         :: "r"(ds), "l"(ss));
        }
    };

    prefetch(0);
    asm volatile("cp.async.commit_group;");
    prefetch(1);
    asm volatile("cp.async.commit_group;");

    float b1[2][2], b2[2][2], b3[2][2];
    int   i1[2][2], i2[2][2], i3[2][2];
    #pragma unroll
    for (int mt = 0; mt < 2; mt++)
        #pragma unroll
        for (int h = 0; h < 2; h++) {
            b1[mt][h] = -1e30f; b2[mt][h] = -2e30f; b3[mt][h] = -3e30f;
            i1[mt][h] = 0;      i2[mt][h] = 1;      i3[mt][h] = 2;
        }

    for (int tile = 0; tile < NTILES; ++tile) {
        asm volatile("cp.async.wait_group 1;");
        __syncthreads();

        int C[2][8][4];
        #pragma unroll
        for (int mt = 0; mt < 2; mt++)
            #pragma unroll
            for (int nt = 0; nt < 8; nt++)
                #pragma unroll
                for (int r = 0; r < 4; r++) C[mt][nt][r] = 0;

        const uint32_t stoff = (tile % 3) * STAGE;

        #pragma unroll
        for (int s = 0; s < 8; s++) {
            uint32_t a[2][4];
            ldm_x4(a[0], aRow[0] + s * 32);
            ldm_x4(a[1], aRow[1] + s * 32);
            uint32_t b[4][4];
            #pragma unroll
            for (int p = 0; p < 4; p++)
                ldm_x4(b[p], bRow[p] + stoff + s * 32);
            #pragma unroll
            for (int mt = 0; mt < 2; mt++)
                #pragma unroll
                for (int p = 0; p < 4; p++) {
                    mma_s8(C[mt][2 * p],     a[mt], &b[p][0]);
                    mma_s8(C[mt][2 * p + 1], a[mt], &b[p][2]);
                }
        }

        if (tile + 2 < NTILES) prefetch(tile + 2);
        asm volatile("cp.async.commit_group;");

        // ---- epilogue: scale + top-3 update ----
        const float* sgb = (const float*)(St + stoff + QG_BYTES);
        const int bn = tile * NTile;
        #pragma unroll
        for (int nt = 0; nt < 8; nt++) {
            const int nc = wn * 64 + nt * 8 + 2 * lq;
            float2 sg = *(const float2*)&sgb[nc];
            const int n0 = bn + nc;
            #pragma unroll
            for (int mt = 0; mt < 2; mt++)
                #pragma unroll
                for (int h = 0; h < 2; h++) {
                    float sc = sx[mt][h];
                    float v0 = (float)C[mt][nt][2 * h]     * (sc * sg.x);
                    float v1 = (float)C[mt][nt][2 * h + 1] * (sc * sg.y);
                    top3_ins(v0, n0,     b1[mt][h], i1[mt][h], b2[mt][h], i2[mt][h], b3[mt][h], i3[mt][h]);
                    top3_ins(v1, n0 + 1, b1[mt][h], i1[mt][h], b2[mt][h], i2[mt][h], b3[mt][h], i3[mt][h]);
                }
        }
    }

    // ---- cross-lane top-3 reduction within quads ----
    #pragma unroll
    for (int mt = 0; mt < 2; mt++)
        #pragma unroll
        for (int h = 0; h < 2; h++) {
            float a1 = b1[mt][h], a2 = b2[mt][h], a3 = b3[mt][h];
            int   j1 = i1[mt][h], j2 = i2[mt][h], j3 = i3[mt][h];
            #pragma unroll
            for (int off = 1; off <= 2; off <<= 1) {
                float o1 = __shfl_xor_sync(0xFFFFFFFFu, a1, off);
                float o2 = __shfl_xor_sync(0xFFFFFFFFu, a2, off);
                float o3 = __shfl_xor_sync(0xFFFFFFFFu, a3, off);
                int   p1 = __shfl_xor_sync(0xFFFFFFFFu, j1, off);
                int   p2 = __shfl_xor_sync(0xFFFFFFFFu, j2, off);
                int   p3 = __shfl_xor_sync(0xFFFFFFFFu, j3, off);
                top3_ins(o1, p1, a1, j1, a2, j2, a3, j3);
                top3_ins(o2, p2, a1, j1, a2, j2, a3, j3);
                top3_ins(o3, p3, a1, j1, a2, j2, a3, j3);
            }
            if (lq == 0) {
                int row = wm * 32 + mt * 16 + h * 8 + l4;
                int idx = row * 2 + wn;
                b1_s[idx] = a1; b2_s[idx] = a2; b3_s[idx] = a3;
                i1_s[idx] = j1; i2_s[idx] = j2; i3_s[idx] = j3;
            }
        }
    __syncthreads();

    // ---- per-row merge + exact fp32 repair + winner ----
    if (tid < MT) {
        float a1 = b1_s[tid * 2], a2 = b2_s[tid * 2], a3 = b3_s[tid * 2];
        int   j1 = i1_s[tid * 2], j2 = i2_s[tid * 2], j3 = i3_s[tid * 2];
        top3_ins(b1_s[tid * 2 + 1], i1_s[tid * 2 + 1], a1, j1, a2, j2, a3, j3);
        top3_ins(b2_s[tid * 2 + 1], i2_s[tid * 2 + 1], a1, j1, a2, j2, a3, j3);
        top3_ins(b3_s[tid * 2 + 1], i3_s[tid * 2 + 1], a1, j1, a2, j2, a3, j3);

        int win = j1;
        if (a1 - a2 < REPAIR_T) {
            int ncand = (a1 - a3 < REPAIR_T) ? 3 : 2;
            int cand[3] = {j1, j2, j3};
            const float* xr = x + (size_t)(bm + tid) * D;
            float ebest = -1e30f;
            int   ibest = 0x7FFFFFFF;
            for (int c = 0; c < ncand; c++) {
                const float* gr = gf + (size_t)cand[c] * D;
                float e = 0.0f;
                #pragma unroll 8
                for (int k = 0; k < D; k++) e = fmaf(xr[k], gr[k], e);
                e *= d_rnorm[cand[c]];
                if (e > ebest || (e == ebest && cand[c] < ibest)) { ebest = e; ibest = cand[c]; }
            }
            win = ibest;
        }
        swin[tid] = win;
        atomicAdd(&d_counts[win], 1u);
    }
    __syncthreads();

    // ---- segment-sum scatter: each thread owns one dim ----
    for (int r = 0; r < MT; r++) {
        int g = swin[r];
        atomicAdd(&d_sums[(size_t)g * D + tid], x[(size_t)(bm + r) * D + tid]);
    }
}

// ---------------------------------------------------------------------------
__global__ void __launch_bounds__(256) finalize_kernel(const float* __restrict__ gf,
                                                       float* __restrict__ out) {
    int i = blockIdx.x * 256 + threadIdx.x;
    int g = i >> 8;
    unsigned int c = d_counts[g];
    float cnt = (float)(c > 1u ? c : 1u);
    out[i] = 0.99f * gf[i] + 0.01f * (d_sums[i] / cnt);
}

// ---------------------------------------------------------------------------
extern "C" void kernel_launch(void* const* d_in, const int* in_sizes, int n_in,
                              void* d_out, int out_size) {
    const float* x;
    const float* gf;
    if (in_sizes[0] == B_ROWS * D) {
        x  = (const float*)d_in[0];
        gf = (const float*)d_in[1];
    } else {
        x  = (const float*)d_in[1];
        gf = (const float*)d_in[0];
    }
    float* out = (float*)d_out;

    cudaFuncSetAttribute(assign_kernel, cudaFuncAttributeMaxDynamicSharedMemorySize, SMEM_TOTAL);

    prep_x_kernel<<<B_ROWS / 8, 256>>>(x);
    prep_g_kernel<<<N_G, 256>>>(gf);
    assign_kernel<<<B_ROWS / MT, 256, SMEM_TOTAL>>>(x, gf);
    finalize_kernel<<<(N_G * D) / 256, 256>>>(gf, out);
}

// round 12
// speedup vs baseline: 2.2350x; 2.2350x over previous
#include <cuda_runtime.h>
#include <cuda_bf16.h>
#include <stdint.h>
#include <math.h>

#define B_ROWS 16384
#define N_G    8192
#define D      256
#define MT     128
#define NTile  128
#define NSLICE 8                     // N-slices per M-tile
#define SLICEN (N_G / NSLICE)        // 1024 cols per job
#define NCHUNK ((SLICEN / NTile) * 2)// 16 chunks of K=128 per job

#define STRA   264                   // halves per A row (256 + 8 pad)
#define STRB   136                   // halves per B row (128 + 8 pad)

#define SM_A_BYTES (MT * STRA * 2)              // 67584
#define B_STAGE    (NTile * STRB * 2)           // 34816
#define SM_BS      SM_A_BYTES
#define SM_TOP     (SM_BS + 3 * B_STAGE)        // 172032
#define SMEM_TOTAL (SM_TOP + 4096)              // 176128

#define REPAIR_T   1e-1f

// ---------------- device scratch ----------------
__device__ __nv_bfloat16 d_gb[N_G * D];      // normalized g, bf16
__device__ float         d_rnorm[N_G];
__device__ float         d_sums[N_G * D];
__device__ unsigned int  d_counts[N_G];
__device__ float2        d_pb[B_ROWS * NSLICE];  // per (row, slice) top-2 values
__device__ int2          d_pi[B_ROWS * NSLICE];  // per (row, slice) top-2 indices
__device__ int           d_assign[B_ROWS];

// ---------------- helpers ----------------
__device__ __forceinline__ uint32_t smem_u32(const void* p) {
    uint32_t a;
    asm("{ .reg .u64 t; cvta.to.shared.u64 t, %1; cvt.u32.u64 %0, t; }" : "=r"(a) : "l"(p));
    return a;
}
__device__ __forceinline__ uint32_t pack_bf2(float lo, float hi) {
    uint32_t r;
    asm("cvt.rn.bf16x2.f32 %0, %1, %2;" : "=r"(r) : "f"(hi), "f"(lo));
    return r;
}
__device__ __forceinline__ void ldm_x4(uint32_t r[4], uint32_t addr) {
    asm volatile("ldmatrix.sync.aligned.m8n8.x4.shared.b16 {%0,%1,%2,%3}, [%4];"
                 : "=r"(r[0]), "=r"(r[1]), "=r"(r[2]), "=r"(r[3]) : "r"(addr));
}
__device__ __forceinline__ void mma_bf16(float c[4], const uint32_t a[4], const uint32_t b[2]) {
    asm volatile(
        "mma.sync.aligned.m16n8k16.row.col.f32.bf16.bf16.f32 "
        "{%0,%1,%2,%3}, {%4,%5,%6,%7}, {%8,%9}, {%0,%1,%2,%3};"
        : "+f"(c[0]), "+f"(c[1]), "+f"(c[2]), "+f"(c[3])
        : "r"(a[0]), "r"(a[1]), "r"(a[2]), "r"(a[3]), "r"(b[0]), "r"(b[1]));
}
__device__ __forceinline__ void top2_merge(float& b1, int& i1, float& s1, int& j1,
                                           float b2, int i2, float s2, int j2) {
    if (b2 > b1 || (b2 == b1 && i2 < i1)) {
        float cs; int cj;
        if (b1 > s2 || (b1 == s2 && i1 < j2)) { cs = b1; cj = i1; } else { cs = s2; cj = j2; }
        b1 = b2; i1 = i2; s1 = cs; j1 = cj;
    } else if (b2 > s1 || (b2 == s1 && i2 < j1)) {
        s1 = b2; j1 = i2;
    }
}

// ---------------------------------------------------------------------------
// prep: normalize g -> bf16; zero sums/counts; keep rnorm
// ---------------------------------------------------------------------------
__global__ void __launch_bounds__(256) prep_g_kernel(const float* __restrict__ gf) {
    int g = blockIdx.x;
    int t = threadIdx.x;
    float v = gf[g * D + t];
    d_sums[g * D + t] = 0.0f;

    float s = v * v;
    #pragma unroll
    for (int o = 16; o; o >>= 1) s += __shfl_xor_sync(0xFFFFFFFFu, s, o);
    __shared__ float red[8];
    __shared__ float srn;
    if ((t & 31) == 0) red[t >> 5] = s;
    __syncthreads();
    if (t < 8) {
        float r = red[t];
        #pragma unroll
        for (int o = 4; o; o >>= 1) r += __shfl_xor_sync(0xFFu, r, o);
        if (t == 0) {
            float rn = 1.0f / fmaxf(sqrtf(r), 1e-12f);
            srn = rn;
            d_rnorm[g] = rn;
            d_counts[g] = 0u;
        }
    }
    __syncthreads();
    d_gb[g * D + t] = __float2bfloat16(v * srn);
}

// ---------------------------------------------------------------------------
// assign_part: one job = (M-tile, N-slice of 1024). Writes top-2 partials.
//   grid = 1024, 256 thr; 8 warps 4(M)x2(N); identical mainloop to R9.
// ---------------------------------------------------------------------------
__global__ void __launch_bounds__(256, 1)
assign_part_kernel(const float* __restrict__ x) {
    extern __shared__ char smem[];
    char*  As    = smem;                          // [128][264] bf16
    char*  Bs    = smem + SM_BS;                  // [3][128][136] bf16
    float* tb_s  = (float*)(smem + SM_TOP);
    float* ts_s  = tb_s + 256;
    int*   tbi_s = (int*)(ts_s + 256);
    int*   tsi_s = tbi_s + 256;

    const int tid   = threadIdx.x;
    const int lane  = tid & 31;
    const int wid   = tid >> 5;
    const int wm    = wid >> 1;
    const int wn    = wid & 1;
    const int l4    = lane >> 2;
    const int lq    = lane & 3;
    const int g8    = lane >> 3;
    const int r8    = lane & 7;
    const int mtile = blockIdx.x >> 3;
    const int slice = blockIdx.x & 7;
    const int bm    = mtile * MT;
    const int bn0   = slice * SLICEN;

    // ---- build A in SMEM (fused fp32->bf16 convert) ----
    for (int i = tid; i < MT * 64; i += 256) {
        int m = i >> 6, q = i & 63;
        float4 v = *(const float4*)&x[(size_t)(bm + m) * D + q * 4];
        uint2 p;
        p.x = pack_bf2(v.x, v.y);
        p.y = pack_bf2(v.z, v.w);
        *(uint2*)(As + m * (STRA * 2) + q * 8) = p;
    }

    // ---- ldmatrix row-base addresses (R9 layout) ----
    uint32_t aRow[2];
    #pragma unroll
    for (int mt = 0; mt < 2; mt++)
        aRow[mt] = smem_u32(As) +
                   (wm * 32 + mt * 16 + (g8 & 1) * 8 + r8) * (STRA * 2) + (g8 >> 1) * 16;
    uint32_t bRow[4];
    #pragma unroll
    for (int p = 0; p < 4; p++)
        bRow[p] = smem_u32(Bs) +
                  (wn * 64 + p * 16 + (g8 >> 1) * 8 + r8) * (STRB * 2) + (g8 & 1) * 16;

    // ---- B prefetch: chunk t = (tile=t>>1, kc=t&1), stage t%3 ----
    const int nrow = tid >> 1;
    const int half = tid & 1;
    auto prefetchB = [&](int t) {
        int tile = t >> 1, kc = t & 1;
        const __nv_bfloat16* src =
            &d_gb[(size_t)(bn0 + tile * NTile + nrow) * D + kc * 128 + half * 64];
        uint32_t dst = smem_u32(Bs + (t % 3) * B_STAGE + nrow * (STRB * 2) + half * 128);
        #pragma unroll
        for (int q = 0; q < 8; q++)
            asm volatile("cp.async.cg.shared.global [%0], [%1], 16;"
                         :: "r"(dst + q * 16), "l"(src + q * 8));
    };

    prefetchB(0);
    asm volatile("cp.async.commit_group;");
    prefetchB(1);
    asm volatile("cp.async.commit_group;");

    float C[2][8][4];
    float tb[2][2], ts[2][2];
    int   tbi[2][2], tsi[2][2];
    #pragma unroll
    for (int mt = 0; mt < 2; mt++)
        #pragma unroll
        for (int h = 0; h < 2; h++) {
            tb[mt][h] = -1e30f; ts[mt][h] = -1e30f;
            tbi[mt][h] = 0;     tsi[mt][h] = 1;
        }

    for (int t = 0; t < NCHUNK; ++t) {
        const int tile = t >> 1, kc = t & 1;

        asm volatile("cp.async.wait_group 1;");
        __syncthreads();

        if (kc == 0) {
            #pragma unroll
            for (int mt = 0; mt < 2; mt++)
                #pragma unroll
                for (int nt = 0; nt < 8; nt++)
                    #pragma unroll
                    for (int r = 0; r < 4; r++) C[mt][nt][r] = 0.0f;
        }

        const uint32_t stoff = (t % 3) * B_STAGE;
        const uint32_t akoff = kc * 256;

        #pragma unroll
        for (int s = 0; s < 8; s++) {
            uint32_t a[2][4];
            ldm_x4(a[0], aRow[0] + akoff + s * 32);
            ldm_x4(a[1], aRow[1] + akoff + s * 32);
            uint32_t b[4][4];
            #pragma unroll
            for (int p = 0; p < 4; p++)
                ldm_x4(b[p], bRow[p] + stoff + s * 32);
            #pragma unroll
            for (int mt = 0; mt < 2; mt++)
                #pragma unroll
                for (int p = 0; p < 4; p++) {
                    mma_bf16(C[mt][2 * p],     a[mt], &b[p][0]);
                    mma_bf16(C[mt][2 * p + 1], a[mt], &b[p][2]);
                }
        }

        if (t + 2 < NCHUNK) prefetchB(t + 2);
        asm volatile("cp.async.commit_group;");

        if (kc == 1) {
            const int bn = bn0 + tile * NTile;
            #pragma unroll
            for (int nt = 0; nt < 8; nt++) {
                const int n0 = bn + wn * 64 + nt * 8 + 2 * lq;
                #pragma unroll
                for (int mt = 0; mt < 2; mt++)
                    #pragma unroll
                    for (int h = 0; h < 2; h++) {
                        float v0 = C[mt][nt][2 * h];
                        float v1 = C[mt][nt][2 * h + 1];
                        if (v0 > tb[mt][h]) { ts[mt][h] = tb[mt][h]; tsi[mt][h] = tbi[mt][h];
                                              tb[mt][h] = v0; tbi[mt][h] = n0; }
                        else if (v0 > ts[mt][h]) { ts[mt][h] = v0; tsi[mt][h] = n0; }
                        if (v1 > tb[mt][h]) { ts[mt][h] = tb[mt][h]; tsi[mt][h] = tbi[mt][h];
                                              tb[mt][h] = v1; tbi[mt][h] = n0 + 1; }
                        else if (v1 > ts[mt][h]) { ts[mt][h] = v1; tsi[mt][h] = n0 + 1; }
                    }
            }
        }
    }

    // ---- cross-lane top-2 reduction within quads ----
    #pragma unroll
    for (int mt = 0; mt < 2; mt++)
        #pragma unroll
        for (int h = 0; h < 2; h++) {
            float b = tb[mt][h], s = ts[mt][h];
            int   bi = tbi[mt][h], si = tsi[mt][h];
            #pragma unroll
            for (int off = 1; off <= 2; off <<= 1) {
                float ob  = __shfl_xor_sync(0xFFFFFFFFu, b, off);
                float os  = __shfl_xor_sync(0xFFFFFFFFu, s, off);
                int   obi = __shfl_xor_sync(0xFFFFFFFFu, bi, off);
                int   osi = __shfl_xor_sync(0xFFFFFFFFu, si, off);
                top2_merge(b, bi, s, si, ob, obi, os, osi);
            }
            if (lq == 0) {
                int row = wm * 32 + mt * 16 + h * 8 + l4;
                int idx = row * 2 + wn;
                tb_s[idx] = b; ts_s[idx] = s; tbi_s[idx] = bi; tsi_s[idx] = si;
            }
        }
    __syncthreads();

    // ---- per-row final merge across wn halves; write global partial ----
    if (tid < MT) {
        float b = tb_s[tid * 2], s = ts_s[tid * 2];
        int   bi = tbi_s[tid * 2], si = tsi_s[tid * 2];
        top2_merge(b, bi, s, si, tb_s[tid * 2 + 1], tbi_s[tid * 2 + 1],
                   ts_s[tid * 2 + 1], tsi_s[tid * 2 + 1]);
        int o = (bm + tid) * NSLICE + slice;
        d_pb[o] = make_float2(b, s);
        d_pi[o] = make_int2(bi, si);
    }
}

// ---------------------------------------------------------------------------
// merge: fold 8 slice partials per row, exact fp32 repair, pick winner
// ---------------------------------------------------------------------------
__global__ void __launch_bounds__(256) merge_kernel(const float* __restrict__ x,
                                                    const float* __restrict__ gf) {
    int row = blockIdx.x * 256 + threadIdx.x;
    float2 v0 = d_pb[row * NSLICE];
    int2   j0 = d_pi[row * NSLICE];
    float b = v0.x, s = v0.y;
    int   bi = j0.x, si = j0.y;
    #pragma unroll
    for (int sl = 1; sl < NSLICE; sl++) {
        float2 v = d_pb[row * NSLICE + sl];
        int2   j = d_pi[row * NSLICE + sl];
        top2_merge(b, bi, s, si, v.x, j.x, v.y, j.y);
    }

    if (b - s < REPAIR_T) {
        const float* xr = x  + (size_t)row * D;
        const float* ga = gf + (size_t)bi * D;
        const float* gb = gf + (size_t)si * D;
        float va = 0.0f, vb = 0.0f;
        #pragma unroll 8
        for (int k = 0; k < D; k++) {
            float xv = xr[k];
            va = fmaf(xv, ga[k], va);
            vb = fmaf(xv, gb[k], vb);
        }
        va *= d_rnorm[bi];
        vb *= d_rnorm[si];
        if (vb > va || (vb == va && si < bi)) bi = si;
    }
    d_assign[row] = bi;
    atomicAdd(&d_counts[bi], 1u);
}

// ---------------------------------------------------------------------------
// scatter: segment-sum. Block handles 128 rows; thread owns one dim.
// ---------------------------------------------------------------------------
__global__ void __launch_bounds__(256) scatter_kernel(const float* __restrict__ x) {
    __shared__ int swin[128];
    int base = blockIdx.x * 128;
    if (threadIdx.x < 128) swin[threadIdx.x] = d_assign[base + threadIdx.x];
    __syncthreads();
    int tid = threadIdx.x;
    for (int r = 0; r < 128; r++) {
        int g = swin[r];
        atomicAdd(&d_sums[(size_t)g * D + tid], x[(size_t)(base + r) * D + tid]);
    }
}

// ---------------------------------------------------------------------------
// finalize (float4): out = 0.99*g + 0.01 * sums / max(count,1)
// ---------------------------------------------------------------------------
__global__ void __launch_bounds__(256) finalize_kernel(const float* __restrict__ gf,
                                                       float* __restrict__ out) {
    int i4 = blockIdx.x * 256 + threadIdx.x;
    int base = i4 * 4;
    int g = base >> 8;
    unsigned int c = d_counts[g];
    float rc = 0.01f / (float)(c > 1u ? c : 1u);
    float4 gv = *(const float4*)&gf[base];
    float4 sv = *(const float4*)&d_sums[base];
    float4 o;
    o.x = 0.99f * gv.x + sv.x * rc;
    o.y = 0.99f * gv.y + sv.y * rc;
    o.z = 0.99f * gv.z + sv.z * rc;
    o.w = 0.99f * gv.w + sv.w * rc;
    *(float4*)&out[base] = o;
}

// ---------------------------------------------------------------------------
extern "C" void kernel_launch(void* const* d_in, const int* in_sizes, int n_in,
                              void* d_out, int out_size) {
    const float* x;
    const float* gf;
    if (in_sizes[0] == B_ROWS * D) {
        x  = (const float*)d_in[0];
        gf = (const float*)d_in[1];
    } else {
        x  = (const float*)d_in[1];
        gf = (const float*)d_in[0];
    }
    float* out = (float*)d_out;

    cudaFuncSetAttribute(assign_part_kernel, cudaFuncAttributeMaxDynamicSharedMemorySize, SMEM_TOTAL);

    prep_g_kernel<<<N_G, 256>>>(gf);
    assign_part_kernel<<<(B_ROWS / MT) * NSLICE, 256, SMEM_TOTAL>>>(x);
    merge_kernel<<<B_ROWS / 256, 256>>>(x, gf);
    scatter_kernel<<<B_ROWS / 128, 256>>>(x);
    finalize_kernel<<<(N_G * D / 4) / 256, 256>>>(gf, out);
}

// round 13
// speedup vs baseline: 2.6614x; 1.1908x over previous
#include <cuda_runtime.h>
#include <cuda_bf16.h>
#include <stdint.h>
#include <math.h>

#define B_ROWS 16384
#define N_G    8192
#define D      256
#define MT     128
#define NTile  128
#define NTILES (N_G / NTile)        // 64
#define NCHUNK (NTILES * 2)         // 128 chunks of K=128
#define NTHREADS 512

#define STRA   264                  // halves per A row (256 + 8 pad)
#define STRB   136                  // halves per B row (128 + 8 pad)

#define SM_A_BYTES (MT * STRA * 2)              // 67584
#define B_STAGE    (NTile * STRB * 2)           // 34816
#define SM_BS      SM_A_BYTES
#define SM_TOP     (SM_BS + 3 * B_STAGE)        // 172032
#define SM_WIN     (SM_TOP + 8192)
#define SMEM_TOTAL (SM_WIN + 1024)              // 181248

#define REPAIR_T   1e-1f

// ---------------- device scratch ----------------
__device__ __nv_bfloat16 d_gb[N_G * D];     // normalized g, bf16
__device__ float         d_rnorm[N_G];
__device__ float         d_sums[N_G * D];
__device__ unsigned int  d_counts[N_G];

// ---------------- helpers ----------------
__device__ __forceinline__ uint32_t smem_u32(const void* p) {
    uint32_t a;
    asm("{ .reg .u64 t; cvta.to.shared.u64 t, %1; cvt.u32.u64 %0, t; }" : "=r"(a) : "l"(p));
    return a;
}
__device__ __forceinline__ uint32_t pack_bf2(float lo, float hi) {
    uint32_t r;
    asm("cvt.rn.bf16x2.f32 %0, %1, %2;" : "=r"(r) : "f"(hi), "f"(lo));
    return r;
}
__device__ __forceinline__ void ldm_x4(uint32_t r[4], uint32_t addr) {
    asm volatile("ldmatrix.sync.aligned.m8n8.x4.shared.b16 {%0,%1,%2,%3}, [%4];"
                 : "=r"(r[0]), "=r"(r[1]), "=r"(r[2]), "=r"(r[3]) : "r"(addr));
}
__device__ __forceinline__ void mma_bf16(float c[4], const uint32_t a[4], const uint32_t b[2]) {
    asm volatile(
        "mma.sync.aligned.m16n8k16.row.col.f32.bf16.bf16.f32 "
        "{%0,%1,%2,%3}, {%4,%5,%6,%7}, {%8,%9}, {%0,%1,%2,%3};"
        : "+f"(c[0]), "+f"(c[1]), "+f"(c[2]), "+f"(c[3])
        : "r"(a[0]), "r"(a[1]), "r"(a[2]), "r"(a[3]), "r"(b[0]), "r"(b[1]));
}
__device__ __forceinline__ void top2_merge(float& b1, int& i1, float& s1, int& j1,
                                           float b2, int i2, float s2, int j2) {
    if (b2 > b1 || (b2 == b1 && i2 < i1)) {
        float cs; int cj;
        if (b1 > s2 || (b1 == s2 && i1 < j2)) { cs = b1; cj = i1; } else { cs = s2; cj = j2; }
        b1 = b2; i1 = i2; s1 = cs; j1 = cj;
    } else if (b2 > s1 || (b2 == s1 && i2 < j1)) {
        s1 = b2; j1 = i2;
    }
}

// ---------------------------------------------------------------------------
// prep: normalize g -> bf16; zero sums/counts; keep rnorm
// ---------------------------------------------------------------------------
__global__ void __launch_bounds__(256) prep_g_kernel(const float* __restrict__ gf) {
    int g = blockIdx.x;
    int t = threadIdx.x;
    float v = gf[g * D + t];
    d_sums[g * D + t] = 0.0f;

    float s = v * v;
    #pragma unroll
    for (int o = 16; o; o >>= 1) s += __shfl_xor_sync(0xFFFFFFFFu, s, o);
    __shared__ float red[8];
    __shared__ float srn;
    if ((t & 31) == 0) red[t >> 5] = s;
    __syncthreads();
    if (t < 8) {
        float r = red[t];
        #pragma unroll
        for (int o = 4; o; o >>= 1) r += __shfl_xor_sync(0xFFu, r, o);
        if (t == 0) {
            float rn = 1.0f / fmaxf(sqrtf(r), 1e-12f);
            srn = rn;
            d_rnorm[g] = rn;
            d_counts[g] = 0u;
        }
    }
    __syncthreads();
    d_gb[g * D + t] = __float2bfloat16(v * srn);
}

// ---------------------------------------------------------------------------
// main: bf16 m16n8k16 GEMM; 16 warps 4(M)x4(N), warp tile 32x32
//   128 CTAs x 512 thr; 3-stage cp.async ring; 1 barrier per K=128 chunk
// ---------------------------------------------------------------------------
__global__ void __launch_bounds__(NTHREADS, 1)
assign_kernel(const float* __restrict__ x, const float* __restrict__ gf) {
    extern __shared__ char smem[];
    char*  As    = smem;                          // [128][264] bf16
    char*  Bs    = smem + SM_BS;                  // [3][128][136] bf16
    float* tb_s  = (float*)(smem + SM_TOP);       // [128 rows][4 wn]
    float* ts_s  = tb_s + 512;
    int*   tbi_s = (int*)(ts_s + 512);
    int*   tsi_s = tbi_s + 512;
    int*   swin  = (int*)(smem + SM_WIN);

    const int tid  = threadIdx.x;
    const int lane = tid & 31;
    const int wid  = tid >> 5;
    const int wm   = wid >> 2;         // 0..3
    const int wn   = wid & 3;          // 0..3
    const int l4   = lane >> 2;
    const int lq   = lane & 3;
    const int g8   = lane >> 3;
    const int r8   = lane & 7;
    const int bm   = blockIdx.x * MT;

    // ---- build A in SMEM (fused fp32->bf16 convert) ----
    for (int i = tid; i < MT * 64; i += NTHREADS) {
        int m = i >> 6, q = i & 63;
        float4 v = *(const float4*)&x[(size_t)(bm + m) * D + q * 4];
        uint2 p;
        p.x = pack_bf2(v.x, v.y);
        p.y = pack_bf2(v.z, v.w);
        *(uint2*)(As + m * (STRA * 2) + q * 8) = p;
    }

    // ---- ldmatrix row-base addresses ----
    uint32_t aRow[2];
    #pragma unroll
    for (int mt = 0; mt < 2; mt++)
        aRow[mt] = smem_u32(As) +
                   (wm * 32 + mt * 16 + (g8 & 1) * 8 + r8) * (STRA * 2) + (g8 >> 1) * 16;
    uint32_t bRow[2];
    #pragma unroll
    for (int p = 0; p < 2; p++)
        bRow[p] = smem_u32(Bs) +
                  (wn * 32 + p * 16 + (g8 >> 1) * 8 + r8) * (STRB * 2) + (g8 & 1) * 16;

    // ---- B prefetch: chunk t = (tile=t>>1, kc=t&1), stage t%3 ----
    const int nrow = tid >> 2;          // 0..127
    const int quar = tid & 3;           // 0..3 (64B each)
    auto prefetchB = [&](int t) {
        int tile = t >> 1, kc = t & 1;
        const __nv_bfloat16* src =
            &d_gb[(size_t)(tile * NTile + nrow) * D + kc * 128 + quar * 32];
        uint32_t dst = smem_u32(Bs + (t % 3) * B_STAGE + nrow * (STRB * 2) + quar * 64);
        #pragma unroll
        for (int q = 0; q < 4; q++)
            asm volatile("cp.async.cg.shared.global [%0], [%1], 16;"
                         :: "r"(dst + q * 16), "l"(src + q * 8));
    };

    prefetchB(0);
    asm volatile("cp.async.commit_group;");
    prefetchB(1);
    asm volatile("cp.async.commit_group;");

    float C[2][4][4];
    float tb[2][2], ts[2][2];
    int   tbi[2][2], tsi[2][2];
    #pragma unroll
    for (int mt = 0; mt < 2; mt++)
        #pragma unroll
        for (int h = 0; h < 2; h++) {
            tb[mt][h] = -1e30f; ts[mt][h] = -1e30f;
            tbi[mt][h] = 0;     tsi[mt][h] = 1;
        }

    for (int t = 0; t < NCHUNK; ++t) {
        const int tile = t >> 1, kc = t & 1;

        asm volatile("cp.async.wait_group 1;");
        __syncthreads();      // stage t ready; all warps done with stage (t-1)

        if (kc == 0) {
            #pragma unroll
            for (int mt = 0; mt < 2; mt++)
                #pragma unroll
                for (int nt = 0; nt < 4; nt++)
                    #pragma unroll
                    for (int r = 0; r < 4; r++) C[mt][nt][r] = 0.0f;
        }

        const uint32_t stoff = (t % 3) * B_STAGE;
        const uint32_t akoff = kc * 256;

        #pragma unroll
        for (int s = 0; s < 8; s++) {
            uint32_t a[2][4];
            ldm_x4(a[0], aRow[0] + akoff + s * 32);
            ldm_x4(a[1], aRow[1] + akoff + s * 32);
            uint32_t b[2][4];
            ldm_x4(b[0], bRow[0] + stoff + s * 32);
            ldm_x4(b[1], bRow[1] + stoff + s * 32);
            #pragma unroll
            for (int mt = 0; mt < 2; mt++)
                #pragma unroll
                for (int p = 0; p < 2; p++) {
                    mma_bf16(C[mt][2 * p],     a[mt], &b[p][0]);
                    mma_bf16(C[mt][2 * p + 1], a[mt], &b[p][2]);
                }
        }

        if (t + 2 < NCHUNK) prefetchB(t + 2);
        asm volatile("cp.async.commit_group;");

        if (kc == 1) {
            const int bn = tile * NTile;
            #pragma unroll
            for (int nt = 0; nt < 4; nt++) {
                const int n0 = bn + wn * 32 + nt * 8 + 2 * lq;
                #pragma unroll
                for (int mt = 0; mt < 2; mt++)
                    #pragma unroll
                    for (int h = 0; h < 2; h++) {
                        float v0 = C[mt][nt][2 * h];
                        float v1 = C[mt][nt][2 * h + 1];
                        if (v0 > tb[mt][h]) { ts[mt][h] = tb[mt][h]; tsi[mt][h] = tbi[mt][h];
                                              tb[mt][h] = v0; tbi[mt][h] = n0; }
                        else if (v0 > ts[mt][h]) { ts[mt][h] = v0; tsi[mt][h] = n0; }
                        if (v1 > tb[mt][h]) { ts[mt][h] = tb[mt][h]; tsi[mt][h] = tbi[mt][h];
                                              tb[mt][h] = v1; tbi[mt][h] = n0 + 1; }
                        else if (v1 > ts[mt][h]) { ts[mt][h] = v1; tsi[mt][h] = n0 + 1; }
                    }
            }
        }
    }

    // ---- cross-lane top-2 reduction within quads ----
    #pragma unroll
    for (int mt = 0; mt < 2; mt++)
        #pragma unroll
        for (int h = 0; h < 2; h++) {
            float b = tb[mt][h], s = ts[mt][h];
            int   bi = tbi[mt][h], si = tsi[mt][h];
            #pragma unroll
            for (int off = 1; off <= 2; off <<= 1) {
                float ob  = __shfl_xor_sync(0xFFFFFFFFu, b, off);
                float os  = __shfl_xor_sync(0xFFFFFFFFu, s, off);
                int   obi = __shfl_xor_sync(0xFFFFFFFFu, bi, off);
                int   osi = __shfl_xor_sync(0xFFFFFFFFu, si, off);
                top2_merge(b, bi, s, si, ob, obi, os, osi);
            }
            if (lq == 0) {
                int row = wm * 32 + mt * 16 + h * 8 + l4;
                int idx = row * 4 + wn;
                tb_s[idx] = b; ts_s[idx] = s; tbi_s[idx] = bi; tsi_s[idx] = si;
            }
        }
    __syncthreads();

    // ---- per-row merge (4 wn partials) + exact fp32 repair + winner ----
    if (tid < MT) {
        float b = tb_s[tid * 4], s = ts_s[tid * 4];
        int   bi = tbi_s[tid * 4], si = tsi_s[tid * 4];
        #pragma unroll
        for (int q = 1; q < 4; q++)
            top2_merge(b, bi, s, si, tb_s[tid * 4 + q], tbi_s[tid * 4 + q],
                       ts_s[tid * 4 + q], tsi_s[tid * 4 + q]);

        if (b - s < REPAIR_T) {
            const float* xr = x  + (size_t)(bm + tid) * D;
            const float* ga = gf + (size_t)bi * D;
            const float* gb = gf + (size_t)si * D;
            float va = 0.0f, vb = 0.0f;
            #pragma unroll 8
            for (int k = 0; k < D; k++) {
                float xv = xr[k];
                va = fmaf(xv, ga[k], va);
                vb = fmaf(xv, gb[k], vb);
            }
            va *= d_rnorm[bi];
            vb *= d_rnorm[si];
            if (vb > va || (vb == va && si < bi)) bi = si;
        }
        swin[tid] = bi;
        atomicAdd(&d_counts[bi], 1u);
    }
    __syncthreads();

    // ---- segment-sum scatter: 2 row-halves x 256 dims ----
    {
        int halfsel = tid >> 8;           // 0 or 1
        int dim     = tid & 255;
        for (int r = halfsel * 64; r < halfsel * 64 + 64; r++) {
            int g = swin[r];
            atomicAdd(&d_sums[(size_t)g * D + dim], x[(size_t)(bm + r) * D + dim]);
        }
    }
}

// ---------------------------------------------------------------------------
// finalize (float4): out = 0.99*g + 0.01 * sums / max(count,1)
// ---------------------------------------------------------------------------
__global__ void __launch_bounds__(256) finalize_kernel(const float* __restrict__ gf,
                                                       float* __restrict__ out) {
    int i4 = blockIdx.x * 256 + threadIdx.x;
    int base = i4 * 4;
    int g = base >> 8;
    unsigned int c = d_counts[g];
    float rc = 0.01f / (float)(c > 1u ? c : 1u);
    float4 gv = *(const float4*)&gf[base];
    float4 sv = *(const float4*)&d_sums[base];
    float4 o;
    o.x = 0.99f * gv.x + sv.x * rc;
    o.y = 0.99f * gv.y + sv.y * rc;
    o.z = 0.99f * gv.z + sv.z * rc;
    o.w = 0.99f * gv.w + sv.w * rc;
    *(float4*)&out[base] = o;
}

// ---------------------------------------------------------------------------
extern "C" void kernel_launch(void* const* d_in, const int* in_sizes, int n_in,
                              void* d_out, int out_size) {
    const float* x;
    const float* gf;
    if (in_sizes[0] == B_ROWS * D) {
        x  = (const float*)d_in[0];
        gf = (const float*)d_in[1];
    } else {
        x  = (const float*)d_in[1];
        gf = (const float*)d_in[0];
    }
    float* out = (float*)d_out;

    cudaFuncSetAttribute(assign_kernel, cudaFuncAttributeMaxDynamicSharedMemorySize, SMEM_TOTAL);

    prep_g_kernel<<<N_G, 256>>>(gf);
    assign_kernel<<<B_ROWS / MT, NTHREADS, SMEM_TOTAL>>>(x, gf);
    finalize_kernel<<<(N_G * D / 4) / 256, 256>>>(gf, out);
}

// round 14
// speedup vs baseline: 2.7175x; 1.0211x over previous
#include <cuda_runtime.h>
#include <cuda_bf16.h>
#include <stdint.h>
#include <math.h>

#define B_ROWS 16384
#define N_G    8192
#define D      256
#define MT     112                  // rows per CTA (146 full + 1 tail tile)
#define NBLK   147
#define NTile  128
#define NTILES (N_G / NTile)        // 64
#define NCHUNK (NTILES * 2)         // 128 chunks of K=128
#define NTHREADS 896                // 28 warps = 7 per SMSP exactly

#define STRA   264                  // halves per A row (256 + 8 pad)
#define STRB   136                  // halves per B row (128 + 8 pad)

#define SM_A_BYTES (MT * STRA * 2)              // 59136
#define B_STAGE    (NTile * STRB * 2)           // 34816
#define SM_BS      SM_A_BYTES
#define SM_TOP     (SM_BS + 3 * B_STAGE)        // 163584
#define SM_WIN     (SM_TOP + 7168)              // top arrays: 448*4*4 B
#define SMEM_TOTAL (SM_WIN + 512)               // 171264

#define REPAIR_T   1e-1f

// ---------------- device scratch ----------------
__device__ __nv_bfloat16 d_gb[N_G * D];     // normalized g, bf16
__device__ float         d_rnorm[N_G];
__device__ float         d_sums[N_G * D];
__device__ unsigned int  d_counts[N_G];

// ---------------- helpers ----------------
__device__ __forceinline__ uint32_t smem_u32(const void* p) {
    uint32_t a;
    asm("{ .reg .u64 t; cvta.to.shared.u64 t, %1; cvt.u32.u64 %0, t; }" : "=r"(a) : "l"(p));
    return a;
}
__device__ __forceinline__ uint32_t pack_bf2(float lo, float hi) {
    uint32_t r;
    asm("cvt.rn.bf16x2.f32 %0, %1, %2;" : "=r"(r) : "f"(hi), "f"(lo));
    return r;
}
__device__ __forceinline__ void ldm_x4(uint32_t r[4], uint32_t addr) {
    asm volatile("ldmatrix.sync.aligned.m8n8.x4.shared.b16 {%0,%1,%2,%3}, [%4];"
                 : "=r"(r[0]), "=r"(r[1]), "=r"(r[2]), "=r"(r[3]) : "r"(addr));
}
__device__ __forceinline__ void mma_bf16(float c[4], const uint32_t a[4], const uint32_t b[2]) {
    asm volatile(
        "mma.sync.aligned.m16n8k16.row.col.f32.bf16.bf16.f32 "
        "{%0,%1,%2,%3}, {%4,%5,%6,%7}, {%8,%9}, {%0,%1,%2,%3};"
        : "+f"(c[0]), "+f"(c[1]), "+f"(c[2]), "+f"(c[3])
        : "r"(a[0]), "r"(a[1]), "r"(a[2]), "r"(a[3]), "r"(b[0]), "r"(b[1]));
}
__device__ __forceinline__ void top2_merge(float& b1, int& i1, float& s1, int& j1,
                                           float b2, int i2, float s2, int j2) {
    if (b2 > b1 || (b2 == b1 && i2 < i1)) {
        float cs; int cj;
        if (b1 > s2 || (b1 == s2 && i1 < j2)) { cs = b1; cj = i1; } else { cs = s2; cj = j2; }
        b1 = b2; i1 = i2; s1 = cs; j1 = cj;
    } else if (b2 > s1 || (b2 == s1 && i2 < j1)) {
        s1 = b2; j1 = i2;
    }
}

// ---------------------------------------------------------------------------
// prep: normalize g -> bf16; zero sums/counts; keep rnorm
// ---------------------------------------------------------------------------
__global__ void __launch_bounds__(256) prep_g_kernel(const float* __restrict__ gf) {
    int g = blockIdx.x;
    int t = threadIdx.x;
    float v = gf[g * D + t];
    d_sums[g * D + t] = 0.0f;

    float s = v * v;
    #pragma unroll
    for (int o = 16; o; o >>= 1) s += __shfl_xor_sync(0xFFFFFFFFu, s, o);
    __shared__ float red[8];
    __shared__ float srn;
    if ((t & 31) == 0) red[t >> 5] = s;
    __syncthreads();
    if (t < 8) {
        float r = red[t];
        #pragma unroll
        for (int o = 4; o; o >>= 1) r += __shfl_xor_sync(0xFFu, r, o);
        if (t == 0) {
            float rn = 1.0f / fmaxf(sqrtf(r), 1e-12f);
            srn = rn;
            d_rnorm[g] = rn;
            d_counts[g] = 0u;
        }
    }
    __syncthreads();
    d_gb[g * D + t] = __float2bfloat16(v * srn);
}

// ---------------------------------------------------------------------------
// main: bf16 m16n8k16; 28 warps 7(M)x4(N), warp tile 16x32; 147 CTAs (1 wave)
// ---------------------------------------------------------------------------
__global__ void __launch_bounds__(NTHREADS, 1)
assign_kernel(const float* __restrict__ x, const float* __restrict__ gf) {
    extern __shared__ char smem[];
    char*  As    = smem;                          // [112][264] bf16
    char*  Bs    = smem + SM_BS;                  // [3][128][136] bf16
    float* tb_s  = (float*)(smem + SM_TOP);       // [112 rows][4 wn]
    float* ts_s  = tb_s + 448;
    int*   tbi_s = (int*)(ts_s + 448);
    int*   tsi_s = tbi_s + 448;
    int*   swin  = (int*)(smem + SM_WIN);

    const int tid  = threadIdx.x;
    const int lane = tid & 31;
    const int wid  = tid >> 5;
    const int wm   = wid >> 2;         // 0..6
    const int wn   = wid & 3;          // 0..3
    const int l4   = lane >> 2;
    const int lq   = lane & 3;
    const int g8   = lane >> 3;
    const int r8   = lane & 7;
    const int bm   = blockIdx.x * MT;

    // ---- build A in SMEM (fused fp32->bf16 convert); tail rows clamped ----
    for (int i = tid; i < MT * 64; i += NTHREADS) {
        int m = i >> 6, q = i & 63;
        int row = bm + m;
        if (row > B_ROWS - 1) row = B_ROWS - 1;
        float4 v = *(const float4*)&x[(size_t)row * D + q * 4];
        uint2 p;
        p.x = pack_bf2(v.x, v.y);
        p.y = pack_bf2(v.z, v.w);
        *(uint2*)(As + m * (STRA * 2) + q * 8) = p;
    }

    // ---- ldmatrix row-base addresses ----
    const uint32_t aRow =
        smem_u32(As) + (wm * 16 + (g8 & 1) * 8 + r8) * (STRA * 2) + (g8 >> 1) * 16;
    uint32_t bRow[2];
    #pragma unroll
    for (int p = 0; p < 2; p++)
        bRow[p] = smem_u32(Bs) +
                  (wn * 32 + p * 16 + (g8 >> 1) * 8 + r8) * (STRB * 2) + (g8 & 1) * 16;

    // ---- B prefetch (threads 0..511): chunk t=(tile,kc), stage t%3 ----
    const int nrow = (tid & 511) >> 2;  // 0..127
    const int quar = tid & 3;           // 0..3
    auto prefetchB = [&](int t) {
        if (tid < 512) {
            int tile = t >> 1, kc = t & 1;
            const __nv_bfloat16* src =
                &d_gb[(size_t)(tile * NTile + nrow) * D + kc * 128 + quar * 32];
            uint32_t dst = smem_u32(Bs + (t % 3) * B_STAGE + nrow * (STRB * 2) + quar * 64);
            #pragma unroll
            for (int q = 0; q < 4; q++)
                asm volatile("cp.async.cg.shared.global [%0], [%1], 16;"
                             :: "r"(dst + q * 16), "l"(src + q * 8));
        }
    };

    prefetchB(0);
    asm volatile("cp.async.commit_group;");
    prefetchB(1);
    asm volatile("cp.async.commit_group;");

    float C[4][4];
    float tb[2], ts[2];
    int   tbi[2], tsi[2];
    #pragma unroll
    for (int h = 0; h < 2; h++) {
        tb[h] = -1e30f; ts[h] = -1e30f;
        tbi[h] = 0;     tsi[h] = 1;
    }

    for (int t = 0; t < NCHUNK; ++t) {
        const int tile = t >> 1, kc = t & 1;

        asm volatile("cp.async.wait_group 1;");
        __syncthreads();      // stage t ready; all warps done with stage (t-1)

        if (kc == 0) {
            #pragma unroll
            for (int nt = 0; nt < 4; nt++)
                #pragma unroll
                for (int r = 0; r < 4; r++) C[nt][r] = 0.0f;
        }

        const uint32_t stoff = (t % 3) * B_STAGE;
        const uint32_t akoff = kc * 256;

        #pragma unroll
        for (int s = 0; s < 8; s++) {
            uint32_t a[4];
            ldm_x4(a, aRow + akoff + s * 32);
            uint32_t b[2][4];
            ldm_x4(b[0], bRow[0] + stoff + s * 32);
            ldm_x4(b[1], bRow[1] + stoff + s * 32);
            #pragma unroll
            for (int p = 0; p < 2; p++) {
                mma_bf16(C[2 * p],     a, &b[p][0]);
                mma_bf16(C[2 * p + 1], a, &b[p][2]);
            }
        }

        if (t + 2 < NCHUNK) prefetchB(t + 2);
        asm volatile("cp.async.commit_group;");

        if (kc == 1) {
            const int bn = tile * NTile;
            #pragma unroll
            for (int nt = 0; nt < 4; nt++) {
                const int n0 = bn + wn * 32 + nt * 8 + 2 * lq;
                #pragma unroll
                for (int h = 0; h < 2; h++) {
                    float v0 = C[nt][2 * h];
                    float v1 = C[nt][2 * h + 1];
                    if (v0 > tb[h]) { ts[h] = tb[h]; tsi[h] = tbi[h]; tb[h] = v0; tbi[h] = n0; }
                    else if (v0 > ts[h]) { ts[h] = v0; tsi[h] = n0; }
                    if (v1 > tb[h]) { ts[h] = tb[h]; tsi[h] = tbi[h]; tb[h] = v1; tbi[h] = n0 + 1; }
                    else if (v1 > ts[h]) { ts[h] = v1; tsi[h] = n0 + 1; }
                }
            }
        }
    }

    // ---- cross-lane top-2 reduction within quads ----
    #pragma unroll
    for (int h = 0; h < 2; h++) {
        float b = tb[h], s = ts[h];
        int   bi = tbi[h], si = tsi[h];
        #pragma unroll
        for (int off = 1; off <= 2; off <<= 1) {
            float ob  = __shfl_xor_sync(0xFFFFFFFFu, b, off);
            float os  = __shfl_xor_sync(0xFFFFFFFFu, s, off);
            int   obi = __shfl_xor_sync(0xFFFFFFFFu, bi, off);
            int   osi = __shfl_xor_sync(0xFFFFFFFFu, si, off);
            top2_merge(b, bi, s, si, ob, obi, os, osi);
        }
        if (lq == 0) {
            int row = wm * 16 + h * 8 + l4;     // 0..111
            int idx = row * 4 + wn;
            tb_s[idx] = b; ts_s[idx] = s; tbi_s[idx] = bi; tsi_s[idx] = si;
        }
    }
    __syncthreads();

    // ---- per-row merge (4 wn partials) + exact fp32 repair + winner ----
    if (tid < MT && bm + tid < B_ROWS) {
        float b = tb_s[tid * 4], s = ts_s[tid * 4];
        int   bi = tbi_s[tid * 4], si = tsi_s[tid * 4];
        #pragma unroll
        for (int q = 1; q < 4; q++)
            top2_merge(b, bi, s, si, tb_s[tid * 4 + q], tbi_s[tid * 4 + q],
                       ts_s[tid * 4 + q], tsi_s[tid * 4 + q]);

        if (b - s < REPAIR_T) {
            const float* xr = x  + (size_t)(bm + tid) * D;
            const float* ga = gf + (size_t)bi * D;
            const float* gb = gf + (size_t)si * D;
            float va = 0.0f, vb = 0.0f;
            #pragma unroll 8
            for (int k = 0; k < D; k++) {
                float xv = xr[k];
                va = fmaf(xv, ga[k], va);
                vb = fmaf(xv, gb[k], vb);
            }
            va *= d_rnorm[bi];
            vb *= d_rnorm[si];
            if (vb > va || (vb == va && si < bi)) bi = si;
        }
        swin[tid] = bi;
        atomicAdd(&d_counts[bi], 1u);
    }
    __syncthreads();

    // ---- segment-sum scatter: threads 0..511 = 2 row-halves x 256 dims ----
    if (tid < 512) {
        int halfsel = tid >> 8;           // 0 or 1
        int dim     = tid & 255;
        int r0 = halfsel * 56, r1 = r0 + 56;
        for (int r = r0; r < r1; r++) {
            if (bm + r >= B_ROWS) break;
            int g = swin[r];
            atomicAdd(&d_sums[(size_t)g * D + dim], x[(size_t)(bm + r) * D + dim]);
        }
    }
}

// ---------------------------------------------------------------------------
// finalize (float4): out = 0.99*g + 0.01 * sums / max(count,1)
// ---------------------------------------------------------------------------
__global__ void __launch_bounds__(256) finalize_kernel(const float* __restrict__ gf,
                                                       float* __restrict__ out) {
    int i4 = blockIdx.x * 256 + threadIdx.x;
    int base = i4 * 4;
    int g = base >> 8;
    unsigned int c = d_counts[g];
    float rc = 0.01f / (float)(c > 1u ? c : 1u);
    float4 gv = *(const float4*)&gf[base];
    float4 sv = *(const float4*)&d_sums[base];
    float4 o;
    o.x = 0.99f * gv.x + sv.x * rc;
    o.y = 0.99f * gv.y + sv.y * rc;
    o.z = 0.99f * gv.z + sv.z * rc;
    o.w = 0.99f * gv.w + sv.w * rc;
    *(float4*)&out[base] = o;
}

// ---------------------------------------------------------------------------
extern "C" void kernel_launch(void* const* d_in, const int* in_sizes, int n_in,
                              void* d_out, int out_size) {
    const float* x;
    const float* gf;
    if (in_sizes[0] == B_ROWS * D) {
        x  = (const float*)d_in[0];
        gf = (const float*)d_in[1];
    } else {
        x  = (const float*)d_in[1];
        gf = (const float*)d_in[0];
    }
    float* out = (float*)d_out;

    cudaFuncSetAttribute(assign_kernel, cudaFuncAttributeMaxDynamicSharedMemorySize, SMEM_TOTAL);

    prep_g_kernel<<<N_G, 256>>>(gf);
    assign_kernel<<<NBLK, NTHREADS, SMEM_TOTAL>>>(x, gf);
    finalize_kernel<<<(N_G * D / 4) / 256, 256>>>(gf, out);
}